// round 3
// baseline (speedup 1.0000x reference)
#include <cuda_runtime.h>

#define N_NODES 50000
#define N_EDGES 800000
#define F_INPUT 256
#define HID     64
#define NHEADS  4
#define NG      64

// ---------------- scratch (device globals: no allocation allowed) ----------------
__device__ int   g_deg[N_NODES];
__device__ float g_dinv[N_NODES];
__device__ int   g_rowptr[N_NODES + 1];
__device__ int   g_cursor[N_NODES];
__device__ int   g_csrsrc[N_EDGES];
__device__ float g_t [N_NODES * HID];            // GEMM output before aggregation
__device__ float g_h [N_NODES * HID];            // layer activations
__device__ float g_hh[N_NODES * NHEADS * HID];   // h @ Wg
__device__ float g_as[N_NODES * NHEADS];         // attention src logits
__device__ float g_ad[N_NODES * NHEADS];         // attention dst logits
__device__ float g_gat[N_NODES * NHEADS * HID];  // GAT output
__device__ float g_pool[NG * NHEADS * HID];
__device__ int   g_gstart[NG + 1];

__device__ __forceinline__ float lrelu(float x) { return x > 0.f ? x : 0.2f * x; }

// ---------------- CSR construction ----------------
__global__ void k_zero_deg() {
    int i = blockIdx.x * blockDim.x + threadIdx.x;
    if (i < N_NODES) g_deg[i] = 0;
}

__global__ void k_hist(const int* __restrict__ ei) {
    int e = blockIdx.x * blockDim.x + threadIdx.x;
    if (e < N_EDGES) atomicAdd(&g_deg[ei[N_EDGES + e]], 1);
}

// single block, 1024 threads: exclusive scan of degrees -> rowptr/cursor, dinv
__global__ void k_scan() {
    __shared__ int sm[1024];
    int t = threadIdx.x;
    const int CH = (N_NODES + 1023) / 1024;   // 49
    int base = t * CH;
    int end  = min(base + CH, N_NODES);
    int sum = 0;
    for (int i = base; i < end; i++) sum += g_deg[i];
    sm[t] = sum;
    __syncthreads();
    for (int off = 1; off < 1024; off <<= 1) {
        int v = (t >= off) ? sm[t - off] : 0;
        __syncthreads();
        sm[t] += v;
        __syncthreads();
    }
    int run = sm[t] - sum;   // exclusive prefix
    for (int i = base; i < end; i++) {
        g_rowptr[i] = run;
        g_cursor[i] = run;
        g_dinv[i]   = rsqrtf((float)(g_deg[i] + 1));  // +1 self-loop
        run += g_deg[i];
    }
    if (t == 1023) g_rowptr[N_NODES] = sm[1023];
}

__global__ void k_scatter(const int* __restrict__ ei) {
    int e = blockIdx.x * blockDim.x + threadIdx.x;
    if (e < N_EDGES) {
        int s = ei[e];
        int d = ei[N_EDGES + e];
        int p = atomicAdd(&g_cursor[d], 1);
        g_csrsrc[p] = s;
    }
}

// ---------------- GEMM: C[M x nCols-tile] = A[M x K] @ W[K x nCols] ----------------
// mode 0: A = ext (x),  C = g_t   (K=256, nCols=64)
// mode 1: A = g_h,      C = g_t   (K=64,  nCols=64)
// mode 2: A = g_h,      C = g_hh  (K=64,  nCols=256)
__global__ void k_gemm(const float* __restrict__ Aext, const float* __restrict__ W,
                       int K, int nCols, int mode) {
    const float* A = (mode == 0) ? Aext : g_h;
    float*       C = (mode == 2) ? g_hh : g_t;

    __shared__ float As[16 * 64];  // [k][row]
    __shared__ float Ws[16 * 64];  // [k][col]
    int tid  = threadIdx.x;        // 256 threads
    int m0   = blockIdx.x * 64;
    int colb = blockIdx.y * 64;
    int r   = tid >> 2, seg = tid & 3;     // A load
    int wr  = tid >> 4, wc  = tid & 15;    // W load
    int ty  = tid >> 4, tx  = tid & 15;    // compute: rows ty*4.., cols tx*4..

    float acc[4][4] = {};

    for (int k0 = 0; k0 < K; k0 += 16) {
        float4 av = make_float4(0.f, 0.f, 0.f, 0.f);
        int row = m0 + r;
        if (row < N_NODES) av = *(const float4*)&A[row * K + k0 + seg * 4];
        As[(seg * 4 + 0) * 64 + r] = av.x;
        As[(seg * 4 + 1) * 64 + r] = av.y;
        As[(seg * 4 + 2) * 64 + r] = av.z;
        As[(seg * 4 + 3) * 64 + r] = av.w;
        *(float4*)&Ws[wr * 64 + wc * 4] =
            *(const float4*)&W[(k0 + wr) * nCols + colb + wc * 4];
        __syncthreads();
#pragma unroll
        for (int kk = 0; kk < 16; kk++) {
            float4 a = *(const float4*)&As[kk * 64 + ty * 4];
            float4 b = *(const float4*)&Ws[kk * 64 + tx * 4];
            acc[0][0] += a.x * b.x; acc[0][1] += a.x * b.y; acc[0][2] += a.x * b.z; acc[0][3] += a.x * b.w;
            acc[1][0] += a.y * b.x; acc[1][1] += a.y * b.y; acc[1][2] += a.y * b.z; acc[1][3] += a.y * b.w;
            acc[2][0] += a.z * b.x; acc[2][1] += a.z * b.y; acc[2][2] += a.z * b.z; acc[2][3] += a.z * b.w;
            acc[3][0] += a.w * b.x; acc[3][1] += a.w * b.y; acc[3][2] += a.w * b.z; acc[3][3] += a.w * b.w;
        }
        __syncthreads();
    }
#pragma unroll
    for (int i = 0; i < 4; i++) {
        int row = m0 + ty * 4 + i;
        if (row < N_NODES) {
            float4 o = make_float4(acc[i][0], acc[i][1], acc[i][2], acc[i][3]);
            *(float4*)&C[row * nCols + colb + tx * 4] = o;
        }
    }
}

// ---------------- GCN aggregation: out = relu(D^-1/2 A' D^-1/2 t + b) ----------------
// warp per destination node; lane handles channels {lane, lane+32}
__global__ void k_gcn(const float* __restrict__ bias) {
    int warp = (blockIdx.x * blockDim.x + threadIdx.x) >> 5;
    int lane = threadIdx.x & 31;
    if (warp >= N_NODES) return;
    int dst = warp;
    int r0 = g_rowptr[dst], r1 = g_rowptr[dst + 1];
    float wd = g_dinv[dst];
    const float* __restrict__ t = g_t;
    float acc0 = t[dst * 64 + lane]      * wd;   // self-loop
    float acc1 = t[dst * 64 + 32 + lane] * wd;
    for (int e0 = r0; e0 < r1; e0 += 32) {
        int idx = e0 + lane;
        int s = 0; float w = 0.f;
        if (idx < r1) { s = g_csrsrc[idx]; w = g_dinv[s]; }
        int cnt = min(32, r1 - e0);
        for (int j = 0; j < cnt; j++) {
            int   ss = __shfl_sync(0xffffffffu, s, j);
            float ww = __shfl_sync(0xffffffffu, w, j);
            acc0 += t[ss * 64 + lane]      * ww;
            acc1 += t[ss * 64 + 32 + lane] * ww;
        }
    }
    g_h[dst * 64 + lane]      = fmaxf(acc0 * wd + bias[lane],      0.f);
    g_h[dst * 64 + 32 + lane] = fmaxf(acc1 * wd + bias[32 + lane], 0.f);
}

// ---------------- attention logits: a_s[n,h] = <hh[n,h,:], att_src[h,:]> ----------------
__global__ void k_att(const float* __restrict__ att_src, const float* __restrict__ att_dst) {
    int warp = (blockIdx.x * blockDim.x + threadIdx.x) >> 5;
    int lane = threadIdx.x & 31;
    if (warp >= N_NODES) return;
    int n = warp;
    int head = lane >> 3;
    int q    = lane & 7;
    const float4* hh4 = (const float4*)g_hh;
    float4 v1 = hh4[n * 64 + lane * 2];
    float4 v2 = hh4[n * 64 + lane * 2 + 1];
    const float4* s4 = (const float4*)att_src;
    const float4* d4 = (const float4*)att_dst;
    float4 a1 = s4[head * 16 + q * 2], a2 = s4[head * 16 + q * 2 + 1];
    float4 b1 = d4[head * 16 + q * 2], b2 = d4[head * 16 + q * 2 + 1];
    float ps = v1.x * a1.x + v1.y * a1.y + v1.z * a1.z + v1.w * a1.w
             + v2.x * a2.x + v2.y * a2.y + v2.z * a2.z + v2.w * a2.w;
    float pd = v1.x * b1.x + v1.y * b1.y + v1.z * b1.z + v1.w * b1.w
             + v2.x * b2.x + v2.y * b2.y + v2.z * b2.z + v2.w * b2.w;
#pragma unroll
    for (int off = 1; off < 8; off <<= 1) {
        ps += __shfl_xor_sync(0xffffffffu, ps, off);
        pd += __shfl_xor_sync(0xffffffffu, pd, off);
    }
    if (q == 0) {
        g_as[n * 4 + head] = ps;
        g_ad[n * 4 + head] = pd;
    }
}

__device__ __forceinline__ void onl(float& m, float& s, float e) {
    if (e > m) { s = s * __expf(m - e) + 1.f; m = e; }
    else       { s += __expf(e - m); }
}
__device__ __forceinline__ void comb(float& m1, float& s1, float m2, float s2) {
    if (m2 > m1) { s1 = s1 * __expf(m1 - m2) + s2; m1 = m2; }
    else         { s1 += s2 * __expf(m2 - m1); }
}

// ---------------- GAT: per-dst online softmax + weighted gather, fused ----------------
__global__ void k_gat() {
    int warp = (blockIdx.x * blockDim.x + threadIdx.x) >> 5;
    int lane = threadIdx.x & 31;
    if (warp >= N_NODES) return;
    int dst = warp;
    int r0 = g_rowptr[dst], r1 = g_rowptr[dst + 1];
    const float4* as4 = (const float4*)g_as;
    float4 adv = ((const float4*)g_ad)[dst];

    // phase 1: per-head (max, sum) via online softmax, lane-parallel over edges
    float m0 = -1e30f, m1 = -1e30f, m2 = -1e30f, m3 = -1e30f;
    float s0 = 0.f, s1 = 0.f, s2 = 0.f, s3 = 0.f;
    for (int e = r0 + lane; e < r1; e += 32) {
        int src = g_csrsrc[e];
        float4 av = as4[src];
        onl(m0, s0, lrelu(av.x + adv.x));
        onl(m1, s1, lrelu(av.y + adv.y));
        onl(m2, s2, lrelu(av.z + adv.z));
        onl(m3, s3, lrelu(av.w + adv.w));
    }
    if (lane == 0) {   // self-loop
        float4 av = as4[dst];
        onl(m0, s0, lrelu(av.x + adv.x));
        onl(m1, s1, lrelu(av.y + adv.y));
        onl(m2, s2, lrelu(av.z + adv.z));
        onl(m3, s3, lrelu(av.w + adv.w));
    }
#pragma unroll
    for (int off = 16; off > 0; off >>= 1) {
        float mm, ss;
        mm = __shfl_down_sync(0xffffffffu, m0, off); ss = __shfl_down_sync(0xffffffffu, s0, off); comb(m0, s0, mm, ss);
        mm = __shfl_down_sync(0xffffffffu, m1, off); ss = __shfl_down_sync(0xffffffffu, s1, off); comb(m1, s1, mm, ss);
        mm = __shfl_down_sync(0xffffffffu, m2, off); ss = __shfl_down_sync(0xffffffffu, s2, off); comb(m2, s2, mm, ss);
        mm = __shfl_down_sync(0xffffffffu, m3, off); ss = __shfl_down_sync(0xffffffffu, s3, off); comb(m3, s3, mm, ss);
    }
    m0 = __shfl_sync(0xffffffffu, m0, 0); s0 = __shfl_sync(0xffffffffu, s0, 0);
    m1 = __shfl_sync(0xffffffffu, m1, 0); s1 = __shfl_sync(0xffffffffu, s1, 0);
    m2 = __shfl_sync(0xffffffffu, m2, 0); s2 = __shfl_sync(0xffffffffu, s2, 0);
    m3 = __shfl_sync(0xffffffffu, m3, 0); s3 = __shfl_sync(0xffffffffu, s3, 0);

    // phase 2: channel-parallel weighted gather; lane owns 8 channels of its head
    int head = lane >> 3;
    float mh  = head == 0 ? m0 : head == 1 ? m1 : head == 2 ? m2 : m3;
    float sh  = head == 0 ? s0 : head == 1 ? s1 : head == 2 ? s2 : s3;
    float adh = head == 0 ? adv.x : head == 1 ? adv.y : head == 2 ? adv.z : adv.w;
    float inv = 1.f / sh;

    float a0 = 0.f, a1 = 0.f, a2 = 0.f, a3 = 0.f, a4 = 0.f, a5 = 0.f, a6 = 0.f, a7 = 0.f;
    const float4* hh4 = (const float4*)g_hh;
    {   // self-loop
        float ash = g_as[dst * 4 + head];
        float al  = __expf(lrelu(ash + adh) - mh) * inv;
        float4 v1 = hh4[dst * 64 + lane * 2];
        float4 v2 = hh4[dst * 64 + lane * 2 + 1];
        a0 += v1.x * al; a1 += v1.y * al; a2 += v1.z * al; a3 += v1.w * al;
        a4 += v2.x * al; a5 += v2.y * al; a6 += v2.z * al; a7 += v2.w * al;
    }
    for (int e0 = r0; e0 < r1; e0 += 32) {
        int idx = e0 + lane;
        int sv = (idx < r1) ? g_csrsrc[idx] : 0;
        int cnt = min(32, r1 - e0);
        for (int j = 0; j < cnt; j++) {
            int src = __shfl_sync(0xffffffffu, sv, j);
            float ash = g_as[src * 4 + head];
            float al  = __expf(lrelu(ash + adh) - mh) * inv;
            float4 v1 = hh4[src * 64 + lane * 2];
            float4 v2 = hh4[src * 64 + lane * 2 + 1];
            a0 += v1.x * al; a1 += v1.y * al; a2 += v1.z * al; a3 += v1.w * al;
            a4 += v2.x * al; a5 += v2.y * al; a6 += v2.z * al; a7 += v2.w * al;
        }
    }
    float4* out4 = (float4*)g_gat;
    out4[dst * 64 + lane * 2]     = make_float4(a0, a1, a2, a3);
    out4[dst * 64 + lane * 2 + 1] = make_float4(a4, a5, a6, a7);
}

// ---------------- pooling (batch is sorted) ----------------
__global__ void k_gstart(const int* __restrict__ batch) {
    int n = blockIdx.x * blockDim.x + threadIdx.x;
    if (n >= N_NODES) return;
    int b = batch[n];
    if (n == 0)
        for (int g = 0; g <= b; g++) g_gstart[g] = 0;
    if (n == N_NODES - 1) {
        for (int g = b + 1; g <= NG; g++) g_gstart[g] = N_NODES;
    } else {
        int b2 = batch[n + 1];
        for (int g = b + 1; g <= b2; g++) g_gstart[g] = n + 1;
    }
}

__global__ void k_pool(const float* __restrict__ bg) {
    int g = blockIdx.x, cb = blockIdx.y;
    int c    = threadIdx.x & 63;
    int slot = threadIdx.x >> 6;   // 0..3
    int st = g_gstart[g], en = g_gstart[g + 1];
    float acc = 0.f;
    for (int n = st + slot; n < en; n += 4)
        acc += g_gat[n * 256 + cb * 64 + c];
    __shared__ float sm[256];
    sm[threadIdx.x] = acc;
    __syncthreads();
    if (slot == 0) {
        float tot = sm[c] + sm[64 + c] + sm[128 + c] + sm[192 + c];
        int cnt = en - st;
        float v = (cnt > 0) ? tot / (float)cnt + bg[cb * 64 + c] : 0.f;
        g_pool[g * 256 + cb * 64 + c] = v;
    }
}

// ---------------- final MLP: out[g] = relu(pool @ Wf1 + bf1) @ Wf2 + bf2 ----------------
__global__ void k_mlp(const float* __restrict__ Wf1, const float* __restrict__ bf1,
                      const float* __restrict__ Wf2, const float* __restrict__ bf2,
                      float* __restrict__ out) {
    int g = blockIdx.x;
    int j = threadIdx.x;   // 64 threads
    float acc = bf1[j];
    const float* p = &g_pool[g * 256];
    for (int c = 0; c < 256; c++)
        acc += p[c] * Wf1[c * 64 + j];
    float z = fmaxf(acc, 0.f) * Wf2[j];
#pragma unroll
    for (int off = 16; off > 0; off >>= 1)
        z += __shfl_xor_sync(0xffffffffu, z, off);
    __shared__ float sm[2];
    if ((threadIdx.x & 31) == 0) sm[threadIdx.x >> 5] = z;
    __syncthreads();
    if (threadIdx.x == 0) out[g] = sm[0] + sm[1] + bf2[0];
}

// ---------------- launch ----------------
extern "C" void kernel_launch(void* const* d_in, const int* in_sizes, int n_in,
                              void* d_out, int out_size) {
    const float* x       = (const float*)d_in[0];
    const int*   ei      = (const int*)  d_in[1];
    const int*   batch   = (const int*)  d_in[2];
    const float* W1      = (const float*)d_in[3];
    const float* b1      = (const float*)d_in[4];
    const float* W2      = (const float*)d_in[5];
    const float* b2      = (const float*)d_in[6];
    const float* Wg      = (const float*)d_in[7];
    const float* att_src = (const float*)d_in[8];
    const float* att_dst = (const float*)d_in[9];
    const float* bg      = (const float*)d_in[10];
    const float* Wf1     = (const float*)d_in[11];
    const float* bf1     = (const float*)d_in[12];
    const float* Wf2     = (const float*)d_in[13];
    const float* bf2     = (const float*)d_in[14];
    float* out = (float*)d_out;

    // CSR + normalization
    k_zero_deg<<<(N_NODES + 255) / 256, 256>>>();
    k_hist    <<<(N_EDGES + 255) / 256, 256>>>(ei);
    k_scan    <<<1, 1024>>>();
    k_scatter <<<(N_EDGES + 255) / 256, 256>>>(ei);

    dim3 gemm_grid1((N_NODES + 63) / 64, 1);
    dim3 gemm_grid4((N_NODES + 63) / 64, 4);
    int  warp_blocks = (N_NODES + 7) / 8;   // 8 warps / 256-thread block

    // GCN layer 1
    k_gemm<<<gemm_grid1, 256>>>(x, W1, F_INPUT, 64, 0);
    k_gcn <<<warp_blocks, 256>>>(b1);
    // GCN layer 2
    k_gemm<<<gemm_grid1, 256>>>(x, W2, 64, 64, 1);
    k_gcn <<<warp_blocks, 256>>>(b2);
    // GAT
    k_gemm<<<gemm_grid4, 256>>>(x, Wg, 64, 256, 2);
    k_att <<<warp_blocks, 256>>>(att_src, att_dst);
    k_gat <<<warp_blocks, 256>>>();
    // pooling + MLP head
    k_gstart<<<(N_NODES + 255) / 256, 256>>>(batch);
    k_pool  <<<dim3(NG, 4), 256>>>(bg);
    k_mlp   <<<NG, 64>>>(Wf1, bf1, Wf2, bf2, out);
}

// round 4
// speedup vs baseline: 1.1839x; 1.1839x over previous
#include <cuda_runtime.h>
#include <cuda_bf16.h>

#define N_NODES 50000
#define N_EDGES 800000
#define F_INPUT 256
#define HID     64
#define NHEADS  4
#define NG      64
#define NB_SCAN 196   // ceil(50000/256)

// ---------------- scratch (device globals: no allocation allowed) ----------------
__device__ int   g_deg[N_NODES];
__device__ float g_dinv[N_NODES];
__device__ int   g_rowptr[N_NODES + 1];
__device__ int   g_cursor[N_NODES];
__device__ int   g_csrsrc[N_EDGES];
__device__ int   g_bsum[256];
__device__ int   g_boff[256];
__device__ float g_t [N_NODES * HID];                 // GEMM output before aggregation
__device__ float g_h [N_NODES * HID];                 // layer activations
__device__ __nv_bfloat162 g_hh2[N_NODES * 128];       // h @ Wg, bf16 pairs (256 ch)
__device__ float g_as[N_NODES * NHEADS];              // attention src logits
__device__ float g_ad[N_NODES * NHEADS];              // attention dst logits
__device__ float g_gat[N_NODES * NHEADS * HID];       // GAT output
__device__ float g_pool[NG * NHEADS * HID];
__device__ int   g_gstart[NG + 1];

__device__ __forceinline__ float lrelu(float x) { return x > 0.f ? x : 0.2f * x; }

// packed fp32 FMA helpers (FFMA2)
__device__ __forceinline__ void fma2(unsigned long long& d, unsigned long long a,
                                     unsigned long long b) {
    asm("fma.rn.f32x2 %0, %1, %2, %0;" : "+l"(d) : "l"(a), "l"(b));
}
__device__ __forceinline__ float2 unpack2(unsigned long long v) {
    float2 f;
    asm("mov.b64 {%0, %1}, %2;" : "=f"(f.x), "=f"(f.y) : "l"(v));
    return f;
}

// ---------------- CSR construction ----------------
__global__ void k_zero_deg() {
    int i = blockIdx.x * blockDim.x + threadIdx.x;
    if (i < N_NODES) g_deg[i] = 0;
}

__global__ void k_hist(const int* __restrict__ ei) {
    int t = blockIdx.x * blockDim.x + threadIdx.x;
    int e = t * 4;
    if (e < N_EDGES) {
        int4 d = *(const int4*)&ei[N_EDGES + e];
        atomicAdd(&g_deg[d.x], 1);
        atomicAdd(&g_deg[d.y], 1);
        atomicAdd(&g_deg[d.z], 1);
        atomicAdd(&g_deg[d.w], 1);
    }
}

// block-local exclusive scan of degrees
__global__ void k_scan_local() {
    __shared__ int sm[256];
    int t = threadIdx.x;
    int i = blockIdx.x * 256 + t;
    int d = (i < N_NODES) ? g_deg[i] : 0;
    sm[t] = d;
    __syncthreads();
    for (int off = 1; off < 256; off <<= 1) {
        int u = (t >= off) ? sm[t - off] : 0;
        __syncthreads();
        sm[t] += u;
        __syncthreads();
    }
    int incl = sm[t];
    if (i < N_NODES) {
        g_rowptr[i] = incl - d;           // local exclusive prefix (fixed up later)
        g_dinv[i]   = rsqrtf((float)(d + 1));
    }
    if (t == 255) g_bsum[blockIdx.x] = incl;
}

// scan the 196 block sums (single block)
__global__ void k_scan_bsum() {
    __shared__ int sm[256];
    int t = threadIdx.x;
    int v = (t < NB_SCAN) ? g_bsum[t] : 0;
    sm[t] = v;
    __syncthreads();
    for (int off = 1; off < 256; off <<= 1) {
        int u = (t >= off) ? sm[t - off] : 0;
        __syncthreads();
        sm[t] += u;
        __syncthreads();
    }
    g_boff[t] = sm[t] - v;
    if (t == 0) g_rowptr[N_NODES] = N_EDGES;
}

__global__ void k_fixup() {
    int i = blockIdx.x * 256 + threadIdx.x;
    if (i < N_NODES) {
        int r = g_rowptr[i] + g_boff[blockIdx.x];
        g_rowptr[i] = r;
        g_cursor[i] = r;
    }
}

__global__ void k_scatter(const int* __restrict__ ei) {
    int t = blockIdx.x * blockDim.x + threadIdx.x;
    int e = t * 4;
    if (e < N_EDGES) {
        int4 s = *(const int4*)&ei[e];
        int4 d = *(const int4*)&ei[N_EDGES + e];
        g_csrsrc[atomicAdd(&g_cursor[d.x], 1)] = s.x;
        g_csrsrc[atomicAdd(&g_cursor[d.y], 1)] = s.y;
        g_csrsrc[atomicAdd(&g_cursor[d.z], 1)] = s.z;
        g_csrsrc[atomicAdd(&g_cursor[d.w], 1)] = s.w;
    }
}

// ---------------- GEMM with FFMA2: C[128 x 64-tile] = A[128 x K] @ W[K x nCols] ----
// mode 0: A = ext (x),  C = g_t   (K=256, nCols=64)  fp32 out
// mode 1: A = g_h,      C = g_t   (K=64,  nCols=64)  fp32 out
// mode 2: A = g_h,      C = g_hh2 (K=64,  nCols=256) bf16 out
#define TCHUNK 32
__global__ __launch_bounds__(256) void k_gemm(const float* __restrict__ Aext,
                                              const float* __restrict__ W,
                                              int K, int nCols, int mode) {
    const float* __restrict__ A = (mode == 0) ? Aext : g_h;

    // A: row-pair-interleaved: Asp[rp][k][parity] = A[2rp+parity][k]
    __shared__ float Asp[64][TCHUNK + 2][2];   // 17408 B
    __shared__ float Wsd[TCHUNK][64][2];       // 16384 B, value duplicated (b,b)

    int tid = threadIdx.x;
    int ty = tid >> 4, tx = tid & 15;          // 16 x 16 thread grid
    int m0 = blockIdx.x * 128;
    int colb = blockIdx.y * 64;

    unsigned long long acc[4][4] = {};         // [row-pair][col], zero = (0.f,0.f)

    for (int k0 = 0; k0 < K; k0 += TCHUNK) {
        // fill A tile (128 x 32)
#pragma unroll
        for (int i = 0; i < 4; i++) {
            int idx = tid + 256 * i;           // 0..1023
            int kseg = idx & 7;                // k offset = kseg*4
            int row = idx >> 3;                // 0..127
            float4 av = make_float4(0.f, 0.f, 0.f, 0.f);
            int grow = m0 + row;
            if (grow < N_NODES)
                av = *(const float4*)&A[(long)grow * K + k0 + kseg * 4];
            int rp = row >> 1, par = row & 1;
            Asp[rp][kseg * 4 + 0][par] = av.x;
            Asp[rp][kseg * 4 + 1][par] = av.y;
            Asp[rp][kseg * 4 + 2][par] = av.z;
            Asp[rp][kseg * 4 + 3][par] = av.w;
        }
        // fill W tile (32 x 64), duplicated
#pragma unroll
        for (int i = 0; i < 8; i++) {
            int e = tid + 256 * i;             // 0..2047
            int kk = e >> 6, c = e & 63;
            float w = W[(long)(k0 + kk) * nCols + colb + c];
            Wsd[kk][c][0] = w;
            Wsd[kk][c][1] = w;
        }
        __syncthreads();

#pragma unroll 4
        for (int kk = 0; kk < TCHUNK; kk++) {
            unsigned long long a[4];
#pragma unroll
            for (int lp = 0; lp < 4; lp++)
                a[lp] = *(const unsigned long long*)&Asp[ty * 4 + lp][kk][0];
            ulonglong2 bA = *(const ulonglong2*)&Wsd[kk][tx * 4][0];
            ulonglong2 bB = *(const ulonglong2*)&Wsd[kk][tx * 4 + 2][0];
#pragma unroll
            for (int lp = 0; lp < 4; lp++) {
                fma2(acc[lp][0], a[lp], bA.x);
                fma2(acc[lp][1], a[lp], bA.y);
                fma2(acc[lp][2], a[lp], bB.x);
                fma2(acc[lp][3], a[lp], bB.y);
            }
        }
        __syncthreads();
    }

    // epilogue
#pragma unroll
    for (int lp = 0; lp < 4; lp++) {
        int rlo = m0 + ty * 8 + 2 * lp;
        float2 u0 = unpack2(acc[lp][0]);
        float2 u1 = unpack2(acc[lp][1]);
        float2 u2 = unpack2(acc[lp][2]);
        float2 u3 = unpack2(acc[lp][3]);
        if (mode != 2) {
            if (rlo < N_NODES)
                *(float4*)&g_t[rlo * 64 + tx * 4] = make_float4(u0.x, u1.x, u2.x, u3.x);
            if (rlo + 1 < N_NODES)
                *(float4*)&g_t[(rlo + 1) * 64 + tx * 4] = make_float4(u0.y, u1.y, u2.y, u3.y);
        } else {
            int cb = (colb >> 1) + tx * 2;     // bf162 column index
            if (rlo < N_NODES) {
                g_hh2[rlo * 128 + cb]     = __floats2bfloat162_rn(u0.x, u1.x);
                g_hh2[rlo * 128 + cb + 1] = __floats2bfloat162_rn(u2.x, u3.x);
            }
            if (rlo + 1 < N_NODES) {
                g_hh2[(rlo + 1) * 128 + cb]     = __floats2bfloat162_rn(u0.y, u1.y);
                g_hh2[(rlo + 1) * 128 + cb + 1] = __floats2bfloat162_rn(u2.y, u3.y);
            }
        }
    }
}

// ---------------- GCN aggregation: out = relu(D^-1/2 A' D^-1/2 t + b) ----------------
__global__ void k_gcn(const float* __restrict__ bias) {
    int warp = (blockIdx.x * blockDim.x + threadIdx.x) >> 5;
    int lane = threadIdx.x & 31;
    if (warp >= N_NODES) return;
    int dst = warp;
    int r0 = g_rowptr[dst], r1 = g_rowptr[dst + 1];
    float wd = g_dinv[dst];
    const float* __restrict__ t = g_t;
    float acc0 = t[dst * 64 + lane]      * wd;   // self-loop
    float acc1 = t[dst * 64 + 32 + lane] * wd;
    for (int e0 = r0; e0 < r1; e0 += 32) {
        int idx = e0 + lane;
        int s = 0; float w = 0.f;
        if (idx < r1) { s = g_csrsrc[idx]; w = g_dinv[s]; }
        int cnt = min(32, r1 - e0);
        for (int j = 0; j < cnt; j++) {
            int   ss = __shfl_sync(0xffffffffu, s, j);
            float ww = __shfl_sync(0xffffffffu, w, j);
            acc0 += t[ss * 64 + lane]      * ww;
            acc1 += t[ss * 64 + 32 + lane] * ww;
        }
    }
    g_h[dst * 64 + lane]      = fmaxf(acc0 * wd + bias[lane],      0.f);
    g_h[dst * 64 + 32 + lane] = fmaxf(acc1 * wd + bias[32 + lane], 0.f);
}

// ---------------- attention logits from bf16 hh ----------------
__global__ void k_att(const float* __restrict__ att_src, const float* __restrict__ att_dst) {
    int warp = (blockIdx.x * blockDim.x + threadIdx.x) >> 5;
    int lane = threadIdx.x & 31;
    if (warp >= N_NODES) return;
    int n = warp;
    int head = lane >> 3;
    int q    = lane & 7;
    float4 raw = *(const float4*)&g_hh2[n * 128 + lane * 4];   // 8 channels
    const __nv_bfloat162* bp = (const __nv_bfloat162*)&raw;
    float2 f0 = __bfloat1622float2(bp[0]);
    float2 f1 = __bfloat1622float2(bp[1]);
    float2 f2 = __bfloat1622float2(bp[2]);
    float2 f3 = __bfloat1622float2(bp[3]);
    const float4* s4 = (const float4*)att_src;
    const float4* d4 = (const float4*)att_dst;
    float4 a1 = s4[head * 16 + q * 2], a2 = s4[head * 16 + q * 2 + 1];
    float4 b1 = d4[head * 16 + q * 2], b2 = d4[head * 16 + q * 2 + 1];
    float ps = f0.x * a1.x + f0.y * a1.y + f1.x * a1.z + f1.y * a1.w
             + f2.x * a2.x + f2.y * a2.y + f3.x * a2.z + f3.y * a2.w;
    float pd = f0.x * b1.x + f0.y * b1.y + f1.x * b1.z + f1.y * b1.w
             + f2.x * b2.x + f2.y * b2.y + f3.x * b2.z + f3.y * b2.w;
#pragma unroll
    for (int off = 1; off < 8; off <<= 1) {
        ps += __shfl_xor_sync(0xffffffffu, ps, off);
        pd += __shfl_xor_sync(0xffffffffu, pd, off);
    }
    if (q == 0) {
        g_as[n * 4 + head] = ps;
        g_ad[n * 4 + head] = pd;
    }
}

__device__ __forceinline__ void onl(float& m, float& s, float e) {
    if (e > m) { s = s * __expf(m - e) + 1.f; m = e; }
    else       { s += __expf(e - m); }
}
__device__ __forceinline__ void comb(float& m1, float& s1, float m2, float s2) {
    if (m2 > m1) { s1 = s1 * __expf(m1 - m2) + s2; m1 = m2; }
    else         { s1 += s2 * __expf(m2 - m1); }
}

// ---------------- GAT: per-dst online softmax + weighted bf16 gather ----------------
__global__ void k_gat() {
    int warp = (blockIdx.x * blockDim.x + threadIdx.x) >> 5;
    int lane = threadIdx.x & 31;
    if (warp >= N_NODES) return;
    int dst = warp;
    int r0 = g_rowptr[dst], r1 = g_rowptr[dst + 1];
    const float4* as4 = (const float4*)g_as;
    float4 adv = ((const float4*)g_ad)[dst];

    // phase 1: per-head (max, sum), lane-parallel over edges
    float m0 = -1e30f, m1 = -1e30f, m2 = -1e30f, m3 = -1e30f;
    float s0 = 0.f, s1 = 0.f, s2 = 0.f, s3 = 0.f;
    for (int e = r0 + lane; e < r1; e += 32) {
        int src = g_csrsrc[e];
        float4 av = as4[src];
        onl(m0, s0, lrelu(av.x + adv.x));
        onl(m1, s1, lrelu(av.y + adv.y));
        onl(m2, s2, lrelu(av.z + adv.z));
        onl(m3, s3, lrelu(av.w + adv.w));
    }
    if (lane == 0) {   // self-loop
        float4 av = as4[dst];
        onl(m0, s0, lrelu(av.x + adv.x));
        onl(m1, s1, lrelu(av.y + adv.y));
        onl(m2, s2, lrelu(av.z + adv.z));
        onl(m3, s3, lrelu(av.w + adv.w));
    }
#pragma unroll
    for (int off = 16; off > 0; off >>= 1) {
        float mm, ss;
        mm = __shfl_down_sync(0xffffffffu, m0, off); ss = __shfl_down_sync(0xffffffffu, s0, off); comb(m0, s0, mm, ss);
        mm = __shfl_down_sync(0xffffffffu, m1, off); ss = __shfl_down_sync(0xffffffffu, s1, off); comb(m1, s1, mm, ss);
        mm = __shfl_down_sync(0xffffffffu, m2, off); ss = __shfl_down_sync(0xffffffffu, s2, off); comb(m2, s2, mm, ss);
        mm = __shfl_down_sync(0xffffffffu, m3, off); ss = __shfl_down_sync(0xffffffffu, s3, off); comb(m3, s3, mm, ss);
    }
    m0 = __shfl_sync(0xffffffffu, m0, 0); s0 = __shfl_sync(0xffffffffu, s0, 0);
    m1 = __shfl_sync(0xffffffffu, m1, 0); s1 = __shfl_sync(0xffffffffu, s1, 0);
    m2 = __shfl_sync(0xffffffffu, m2, 0); s2 = __shfl_sync(0xffffffffu, s2, 0);
    m3 = __shfl_sync(0xffffffffu, m3, 0); s3 = __shfl_sync(0xffffffffu, s3, 0);

    // phase 2: channel-parallel weighted gather (bf16 hh); lane owns 8 ch of its head
    int head = lane >> 3;
    float mh  = head == 0 ? m0 : head == 1 ? m1 : head == 2 ? m2 : m3;
    float sh  = head == 0 ? s0 : head == 1 ? s1 : head == 2 ? s2 : s3;
    float adh = head == 0 ? adv.x : head == 1 ? adv.y : head == 2 ? adv.z : adv.w;
    float inv = 1.f / sh;

    float a0 = 0.f, a1 = 0.f, a2 = 0.f, a3 = 0.f, a4 = 0.f, a5 = 0.f, a6 = 0.f, a7 = 0.f;
    {   // self-loop
        float ash = g_as[dst * 4 + head];
        float al  = __expf(lrelu(ash + adh) - mh) * inv;
        float4 raw = *(const float4*)&g_hh2[dst * 128 + lane * 4];
        const __nv_bfloat162* bp = (const __nv_bfloat162*)&raw;
        float2 f0 = __bfloat1622float2(bp[0]);
        float2 f1 = __bfloat1622float2(bp[1]);
        float2 f2 = __bfloat1622float2(bp[2]);
        float2 f3 = __bfloat1622float2(bp[3]);
        a0 += f0.x * al; a1 += f0.y * al; a2 += f1.x * al; a3 += f1.y * al;
        a4 += f2.x * al; a5 += f2.y * al; a6 += f3.x * al; a7 += f3.y * al;
    }
    for (int e0 = r0; e0 < r1; e0 += 32) {
        int idx = e0 + lane;
        int sv = (idx < r1) ? g_csrsrc[idx] : 0;
        int cnt = min(32, r1 - e0);
        for (int j = 0; j < cnt; j++) {
            int src = __shfl_sync(0xffffffffu, sv, j);
            float ash = g_as[src * 4 + head];
            float al  = __expf(lrelu(ash + adh) - mh) * inv;
            float4 raw = *(const float4*)&g_hh2[src * 128 + lane * 4];
            const __nv_bfloat162* bp = (const __nv_bfloat162*)&raw;
            float2 f0 = __bfloat1622float2(bp[0]);
            float2 f1 = __bfloat1622float2(bp[1]);
            float2 f2 = __bfloat1622float2(bp[2]);
            float2 f3 = __bfloat1622float2(bp[3]);
            a0 += f0.x * al; a1 += f0.y * al; a2 += f1.x * al; a3 += f1.y * al;
            a4 += f2.x * al; a5 += f2.y * al; a6 += f3.x * al; a7 += f3.y * al;
        }
    }
    float4* out4 = (float4*)g_gat;
    out4[dst * 64 + lane * 2]     = make_float4(a0, a1, a2, a3);
    out4[dst * 64 + lane * 2 + 1] = make_float4(a4, a5, a6, a7);
}

// ---------------- pooling (batch is sorted) ----------------
__global__ void k_gstart(const int* __restrict__ batch) {
    int n = blockIdx.x * blockDim.x + threadIdx.x;
    if (n >= N_NODES) return;
    int b = batch[n];
    if (n == 0)
        for (int g = 0; g <= b; g++) g_gstart[g] = 0;
    if (n == N_NODES - 1) {
        for (int g = b + 1; g <= NG; g++) g_gstart[g] = N_NODES;
    } else {
        int b2 = batch[n + 1];
        for (int g = b + 1; g <= b2; g++) g_gstart[g] = n + 1;
    }
}

__global__ void k_pool(const float* __restrict__ bg) {
    int g = blockIdx.x, cb = blockIdx.y;
    int c    = threadIdx.x & 63;
    int slot = threadIdx.x >> 6;   // 0..3
    int st = g_gstart[g], en = g_gstart[g + 1];
    float acc = 0.f;
    for (int n = st + slot; n < en; n += 4)
        acc += g_gat[n * 256 + cb * 64 + c];
    __shared__ float sm[256];
    sm[threadIdx.x] = acc;
    __syncthreads();
    if (slot == 0) {
        float tot = sm[c] + sm[64 + c] + sm[128 + c] + sm[192 + c];
        int cnt = en - st;
        float v = (cnt > 0) ? tot / (float)cnt + bg[cb * 64 + c] : 0.f;
        g_pool[g * 256 + cb * 64 + c] = v;
    }
}

// ---------------- final MLP ----------------
__global__ void k_mlp(const float* __restrict__ Wf1, const float* __restrict__ bf1,
                      const float* __restrict__ Wf2, const float* __restrict__ bf2,
                      float* __restrict__ out) {
    int g = blockIdx.x;
    int j = threadIdx.x;   // 64 threads
    float acc = bf1[j];
    const float* p = &g_pool[g * 256];
    for (int c = 0; c < 256; c++)
        acc += p[c] * Wf1[c * 64 + j];
    float z = fmaxf(acc, 0.f) * Wf2[j];
#pragma unroll
    for (int off = 16; off > 0; off >>= 1)
        z += __shfl_xor_sync(0xffffffffu, z, off);
    __shared__ float sm[2];
    if ((threadIdx.x & 31) == 0) sm[threadIdx.x >> 5] = z;
    __syncthreads();
    if (threadIdx.x == 0) out[g] = sm[0] + sm[1] + bf2[0];
}

// ---------------- launch ----------------
extern "C" void kernel_launch(void* const* d_in, const int* in_sizes, int n_in,
                              void* d_out, int out_size) {
    const float* x       = (const float*)d_in[0];
    const int*   ei      = (const int*)  d_in[1];
    const int*   batch   = (const int*)  d_in[2];
    const float* W1      = (const float*)d_in[3];
    const float* b1      = (const float*)d_in[4];
    const float* W2      = (const float*)d_in[5];
    const float* b2      = (const float*)d_in[6];
    const float* Wg      = (const float*)d_in[7];
    const float* att_src = (const float*)d_in[8];
    const float* att_dst = (const float*)d_in[9];
    const float* bg      = (const float*)d_in[10];
    const float* Wf1     = (const float*)d_in[11];
    const float* bf1     = (const float*)d_in[12];
    const float* Wf2     = (const float*)d_in[13];
    const float* bf2     = (const float*)d_in[14];
    float* out = (float*)d_out;

    // CSR + normalization (parallel scan)
    k_zero_deg <<<(N_NODES + 255) / 256, 256>>>();
    k_hist     <<<(N_EDGES / 4 + 255) / 256, 256>>>(ei);
    k_scan_local<<<NB_SCAN, 256>>>();
    k_scan_bsum <<<1, 256>>>();
    k_fixup     <<<NB_SCAN, 256>>>();
    k_scatter  <<<(N_EDGES / 4 + 255) / 256, 256>>>(ei);

    dim3 gemm_grid1((N_NODES + 127) / 128, 1);
    dim3 gemm_grid4((N_NODES + 127) / 128, 4);
    int  warp_blocks = (N_NODES + 7) / 8;   // 8 warps / 256-thread block

    // GCN layer 1
    k_gemm<<<gemm_grid1, 256>>>(x, W1, F_INPUT, 64, 0);
    k_gcn <<<warp_blocks, 256>>>(b1);
    // GCN layer 2
    k_gemm<<<gemm_grid1, 256>>>(x, W2, 64, 64, 1);
    k_gcn <<<warp_blocks, 256>>>(b2);
    // GAT
    k_gemm<<<gemm_grid4, 256>>>(x, Wg, 64, 256, 2);
    k_att <<<warp_blocks, 256>>>(att_src, att_dst);
    k_gat <<<warp_blocks, 256>>>();
    // pooling + MLP head
    k_gstart<<<(N_NODES + 255) / 256, 256>>>(batch);
    k_pool  <<<dim3(NG, 4), 256>>>(bg);
    k_mlp   <<<NG, 64>>>(Wf1, bf1, Wf2, bf2, out);
}

// round 5
// speedup vs baseline: 1.2774x; 1.0790x over previous
#include <cuda_runtime.h>
#include <cuda_bf16.h>

#define N_NODES 50000
#define N_EDGES 800000
#define F_INPUT 256
#define HID     64
#define NHEADS  4
#define NG      64
#define NB_SCAN 196   // ceil(50000/256)

// ---------------- scratch (device globals: no allocation allowed) ----------------
__device__ int   g_deg[N_NODES];
__device__ float g_dinv[N_NODES];
__device__ int   g_rowptr[N_NODES + 1];
__device__ int   g_cursor[N_NODES];
__device__ int   g_csrsrc[N_EDGES];
__device__ int   g_bsum[256];
__device__ int   g_boff[256];
__device__ __nv_bfloat162 g_t2[N_NODES * 32];         // GEMM out (64 ch as bf16 pairs)
__device__ float g_h [N_NODES * HID];                 // layer activations (fp32)
__device__ __nv_bfloat162 g_hh2[N_NODES * 128];       // h @ Wg, bf16 pairs (256 ch)
__device__ float g_as[N_NODES * NHEADS];              // attention src logits
__device__ float g_ad[N_NODES * NHEADS];              // attention dst logits
__device__ float g_gat[N_NODES * NHEADS * HID];       // GAT output
__device__ float g_pool[NG * NHEADS * HID];
__device__ int   g_gstart[NG + 1];

__device__ __forceinline__ float lrelu(float x) { return x > 0.f ? x : 0.2f * x; }

// packed fp32 FMA helpers (FFMA2)
__device__ __forceinline__ void fma2(unsigned long long& d, unsigned long long a,
                                     unsigned long long b) {
    asm("fma.rn.f32x2 %0, %1, %2, %0;" : "+l"(d) : "l"(a), "l"(b));
}
__device__ __forceinline__ float2 unpack2(unsigned long long v) {
    float2 f;
    asm("mov.b64 {%0, %1}, %2;" : "=f"(f.x), "=f"(f.y) : "l"(v));
    return f;
}

// ---------------- CSR construction ----------------
__global__ void k_hist(const int* __restrict__ ei) {
    int t = blockIdx.x * blockDim.x + threadIdx.x;
    int e = t * 4;
    if (e < N_EDGES) {
        int4 d = *(const int4*)&ei[N_EDGES + e];
        atomicAdd(&g_deg[d.x], 1);
        atomicAdd(&g_deg[d.y], 1);
        atomicAdd(&g_deg[d.z], 1);
        atomicAdd(&g_deg[d.w], 1);
    }
}

// block-local exclusive scan of degrees
__global__ void k_scan_local() {
    __shared__ int sm[256];
    int t = threadIdx.x;
    int i = blockIdx.x * 256 + t;
    int d = (i < N_NODES) ? g_deg[i] : 0;
    sm[t] = d;
    __syncthreads();
    for (int off = 1; off < 256; off <<= 1) {
        int u = (t >= off) ? sm[t - off] : 0;
        __syncthreads();
        sm[t] += u;
        __syncthreads();
    }
    int incl = sm[t];
    if (i < N_NODES) {
        g_rowptr[i] = incl - d;           // local exclusive prefix (fixed up later)
        g_dinv[i]   = rsqrtf((float)(d + 1));
    }
    if (t == 255) g_bsum[blockIdx.x] = incl;
}

// scan the 196 block sums (single block)
__global__ void k_scan_bsum() {
    __shared__ int sm[256];
    int t = threadIdx.x;
    int v = (t < NB_SCAN) ? g_bsum[t] : 0;
    sm[t] = v;
    __syncthreads();
    for (int off = 1; off < 256; off <<= 1) {
        int u = (t >= off) ? sm[t - off] : 0;
        __syncthreads();
        sm[t] += u;
        __syncthreads();
    }
    g_boff[t] = sm[t] - v;
    if (t == 0) g_rowptr[N_NODES] = N_EDGES;
}

__global__ void k_fixup() {
    int i = blockIdx.x * 256 + threadIdx.x;
    if (i < N_NODES) {
        int r = g_rowptr[i] + g_boff[blockIdx.x];
        g_rowptr[i] = r;
        g_cursor[i] = r;
    }
}

__global__ void k_scatter(const int* __restrict__ ei) {
    int t = blockIdx.x * blockDim.x + threadIdx.x;
    int e = t * 4;
    if (e < N_EDGES) {
        int4 s = *(const int4*)&ei[e];
        int4 d = *(const int4*)&ei[N_EDGES + e];
        g_csrsrc[atomicAdd(&g_cursor[d.x], 1)] = s.x;
        g_csrsrc[atomicAdd(&g_cursor[d.y], 1)] = s.y;
        g_csrsrc[atomicAdd(&g_cursor[d.z], 1)] = s.z;
        g_csrsrc[atomicAdd(&g_cursor[d.w], 1)] = s.w;
    }
}

// ---------------- GEMM with FFMA2: C[128 x 64-tile] = A[128 x K] @ W[K x nCols] ----
// mode 0: A = ext (x),  C = g_t2  (K=256, nCols=64)  bf16 out
// mode 1: A = g_h,      C = g_t2  (K=64,  nCols=64)  bf16 out
// mode 2: A = g_h,      C = g_hh2 (K=64,  nCols=256) bf16 out
#define TCHUNK 32
__global__ __launch_bounds__(256) void k_gemm(const float* __restrict__ Aext,
                                              const float* __restrict__ W,
                                              int K, int nCols, int mode) {
    const float* __restrict__ A = (mode == 0) ? Aext : g_h;

    // A: row-pair-interleaved: Asp[rp][k][parity] = A[2rp+parity][k]
    __shared__ float Asp[64][TCHUNK + 2][2];   // 17408 B
    __shared__ float Wsd[TCHUNK][64][2];       // 16384 B, value duplicated (b,b)

    int tid = threadIdx.x;
    int ty = tid >> 4, tx = tid & 15;          // 16 x 16 thread grid
    int m0 = blockIdx.x * 128;
    int colb = blockIdx.y * 64;

    unsigned long long acc[4][4] = {};         // [row-pair][col], zero = (0.f,0.f)

    for (int k0 = 0; k0 < K; k0 += TCHUNK) {
        // fill A tile (128 x 32)
#pragma unroll
        for (int i = 0; i < 4; i++) {
            int idx = tid + 256 * i;           // 0..1023
            int kseg = idx & 7;                // k offset = kseg*4
            int row = idx >> 3;                // 0..127
            float4 av = make_float4(0.f, 0.f, 0.f, 0.f);
            int grow = m0 + row;
            if (grow < N_NODES)
                av = *(const float4*)&A[(long)grow * K + k0 + kseg * 4];
            int rp = row >> 1, par = row & 1;
            Asp[rp][kseg * 4 + 0][par] = av.x;
            Asp[rp][kseg * 4 + 1][par] = av.y;
            Asp[rp][kseg * 4 + 2][par] = av.z;
            Asp[rp][kseg * 4 + 3][par] = av.w;
        }
        // fill W tile (32 x 64), duplicated
#pragma unroll
        for (int i = 0; i < 8; i++) {
            int e = tid + 256 * i;             // 0..2047
            int kk = e >> 6, c = e & 63;
            float w = W[(long)(k0 + kk) * nCols + colb + c];
            Wsd[kk][c][0] = w;
            Wsd[kk][c][1] = w;
        }
        __syncthreads();

#pragma unroll 4
        for (int kk = 0; kk < TCHUNK; kk++) {
            unsigned long long a[4];
#pragma unroll
            for (int lp = 0; lp < 4; lp++)
                a[lp] = *(const unsigned long long*)&Asp[ty * 4 + lp][kk][0];
            ulonglong2 bA = *(const ulonglong2*)&Wsd[kk][tx * 4][0];
            ulonglong2 bB = *(const ulonglong2*)&Wsd[kk][tx * 4 + 2][0];
#pragma unroll
            for (int lp = 0; lp < 4; lp++) {
                fma2(acc[lp][0], a[lp], bA.x);
                fma2(acc[lp][1], a[lp], bA.y);
                fma2(acc[lp][2], a[lp], bB.x);
                fma2(acc[lp][3], a[lp], bB.y);
            }
        }
        __syncthreads();
    }

    // epilogue: all modes write bf16x2
    __nv_bfloat162* outp = (mode == 2) ? g_hh2 : g_t2;
    int ostride = (mode == 2) ? 128 : 32;
    int cb = ((mode == 2) ? (colb >> 1) : 0) + tx * 2;
#pragma unroll
    for (int lp = 0; lp < 4; lp++) {
        int rlo = m0 + ty * 8 + 2 * lp;
        float2 u0 = unpack2(acc[lp][0]);
        float2 u1 = unpack2(acc[lp][1]);
        float2 u2 = unpack2(acc[lp][2]);
        float2 u3 = unpack2(acc[lp][3]);
        if (rlo < N_NODES) {
            outp[rlo * ostride + cb]     = __floats2bfloat162_rn(u0.x, u1.x);
            outp[rlo * ostride + cb + 1] = __floats2bfloat162_rn(u2.x, u3.x);
        }
        if (rlo + 1 < N_NODES) {
            outp[(rlo + 1) * ostride + cb]     = __floats2bfloat162_rn(u0.y, u1.y);
            outp[(rlo + 1) * ostride + cb + 1] = __floats2bfloat162_rn(u2.y, u3.y);
        }
    }
}

// ---------------- GCN aggregation: h = relu(D^-1/2 A' D^-1/2 t + b) --------------
// warp per destination; lane owns channels {2*lane, 2*lane+1} (bf16x2 loads)
__global__ void k_gcn(const float* __restrict__ bias) {
    int warp = (blockIdx.x * blockDim.x + threadIdx.x) >> 5;
    int lane = threadIdx.x & 31;
    if (warp >= N_NODES) return;
    int dst = warp;
    int r0 = g_rowptr[dst], r1 = g_rowptr[dst + 1];
    float wd = g_dinv[dst];
    const __nv_bfloat162* __restrict__ t2 = g_t2;
    float2 f = __bfloat1622float2(t2[dst * 32 + lane]);   // self-loop
    float acc0 = f.x * wd;
    float acc1 = f.y * wd;
    for (int e0 = r0; e0 < r1; e0 += 32) {
        int idx = e0 + lane;
        int s = 0; float w = 0.f;
        if (idx < r1) { s = g_csrsrc[idx]; w = g_dinv[s]; }
        int cnt = min(32, r1 - e0);
        for (int j = 0; j < cnt; j++) {
            int   ss = __shfl_sync(0xffffffffu, s, j);
            float ww = __shfl_sync(0xffffffffu, w, j);
            float2 v = __bfloat1622float2(t2[ss * 32 + lane]);
            acc0 += v.x * ww;
            acc1 += v.y * ww;
        }
    }
    float2 b = *(const float2*)&bias[2 * lane];
    float2 o;
    o.x = fmaxf(acc0 * wd + b.x, 0.f);
    o.y = fmaxf(acc1 * wd + b.y, 0.f);
    *(float2*)&g_h[dst * 64 + 2 * lane] = o;
}

// ---------------- attention logits from bf16 hh ----------------
__global__ void k_att(const float* __restrict__ att_src, const float* __restrict__ att_dst) {
    int warp = (blockIdx.x * blockDim.x + threadIdx.x) >> 5;
    int lane = threadIdx.x & 31;
    if (warp >= N_NODES) return;
    int n = warp;
    int head = lane >> 3;
    int q    = lane & 7;
    float4 raw = *(const float4*)&g_hh2[n * 128 + lane * 4];   // 8 channels
    const __nv_bfloat162* bp = (const __nv_bfloat162*)&raw;
    float2 f0 = __bfloat1622float2(bp[0]);
    float2 f1 = __bfloat1622float2(bp[1]);
    float2 f2 = __bfloat1622float2(bp[2]);
    float2 f3 = __bfloat1622float2(bp[3]);
    const float4* s4 = (const float4*)att_src;
    const float4* d4 = (const float4*)att_dst;
    float4 a1 = s4[head * 16 + q * 2], a2 = s4[head * 16 + q * 2 + 1];
    float4 b1 = d4[head * 16 + q * 2], b2 = d4[head * 16 + q * 2 + 1];
    float ps = f0.x * a1.x + f0.y * a1.y + f1.x * a1.z + f1.y * a1.w
             + f2.x * a2.x + f2.y * a2.y + f3.x * a2.z + f3.y * a2.w;
    float pd = f0.x * b1.x + f0.y * b1.y + f1.x * b1.z + f1.y * b1.w
             + f2.x * b2.x + f2.y * b2.y + f3.x * b2.z + f3.y * b2.w;
#pragma unroll
    for (int off = 1; off < 8; off <<= 1) {
        ps += __shfl_xor_sync(0xffffffffu, ps, off);
        pd += __shfl_xor_sync(0xffffffffu, pd, off);
    }
    if (q == 0) {
        g_as[n * 4 + head] = ps;
        g_ad[n * 4 + head] = pd;
    }
}

__device__ __forceinline__ void onl(float& m, float& s, float e) {
    if (e > m) { s = s * __expf(m - e) + 1.f; m = e; }
    else       { s += __expf(e - m); }
}
__device__ __forceinline__ void comb(float& m1, float& s1, float m2, float s2) {
    if (m2 > m1) { s1 = s1 * __expf(m1 - m2) + s2; m1 = m2; }
    else         { s1 += s2 * __expf(m2 - m1); }
}

// ---------------- GAT: per-dst online softmax + weighted bf16 gather ----------------
__global__ void k_gat() {
    int warp = (blockIdx.x * blockDim.x + threadIdx.x) >> 5;
    int lane = threadIdx.x & 31;
    if (warp >= N_NODES) return;
    int dst = warp;
    int r0 = g_rowptr[dst], r1 = g_rowptr[dst + 1];
    const float4* as4 = (const float4*)g_as;
    float4 adv = ((const float4*)g_ad)[dst];

    // phase 1: per-head (max, sum), lane-parallel over edges
    float m0 = -1e30f, m1 = -1e30f, m2 = -1e30f, m3 = -1e30f;
    float s0 = 0.f, s1 = 0.f, s2 = 0.f, s3 = 0.f;
    for (int e = r0 + lane; e < r1; e += 32) {
        int src = g_csrsrc[e];
        float4 av = as4[src];
        onl(m0, s0, lrelu(av.x + adv.x));
        onl(m1, s1, lrelu(av.y + adv.y));
        onl(m2, s2, lrelu(av.z + adv.z));
        onl(m3, s3, lrelu(av.w + adv.w));
    }
    if (lane == 0) {   // self-loop
        float4 av = as4[dst];
        onl(m0, s0, lrelu(av.x + adv.x));
        onl(m1, s1, lrelu(av.y + adv.y));
        onl(m2, s2, lrelu(av.z + adv.z));
        onl(m3, s3, lrelu(av.w + adv.w));
    }
#pragma unroll
    for (int off = 16; off > 0; off >>= 1) {
        float mm, ss;
        mm = __shfl_down_sync(0xffffffffu, m0, off); ss = __shfl_down_sync(0xffffffffu, s0, off); comb(m0, s0, mm, ss);
        mm = __shfl_down_sync(0xffffffffu, m1, off); ss = __shfl_down_sync(0xffffffffu, s1, off); comb(m1, s1, mm, ss);
        mm = __shfl_down_sync(0xffffffffu, m2, off); ss = __shfl_down_sync(0xffffffffu, s2, off); comb(m2, s2, mm, ss);
        mm = __shfl_down_sync(0xffffffffu, m3, off); ss = __shfl_down_sync(0xffffffffu, s3, off); comb(m3, s3, mm, ss);
    }
    m0 = __shfl_sync(0xffffffffu, m0, 0); s0 = __shfl_sync(0xffffffffu, s0, 0);
    m1 = __shfl_sync(0xffffffffu, m1, 0); s1 = __shfl_sync(0xffffffffu, s1, 0);
    m2 = __shfl_sync(0xffffffffu, m2, 0); s2 = __shfl_sync(0xffffffffu, s2, 0);
    m3 = __shfl_sync(0xffffffffu, m3, 0); s3 = __shfl_sync(0xffffffffu, s3, 0);

    // phase 2: channel-parallel weighted gather (bf16 hh); lane owns 8 ch of its head
    int head = lane >> 3;
    float mh  = head == 0 ? m0 : head == 1 ? m1 : head == 2 ? m2 : m3;
    float sh  = head == 0 ? s0 : head == 1 ? s1 : head == 2 ? s2 : s3;
    float adh = head == 0 ? adv.x : head == 1 ? adv.y : head == 2 ? adv.z : adv.w;
    float inv = 1.f / sh;

    float a0 = 0.f, a1 = 0.f, a2 = 0.f, a3 = 0.f, a4 = 0.f, a5 = 0.f, a6 = 0.f, a7 = 0.f;
    {   // self-loop
        float ash = g_as[dst * 4 + head];
        float al  = __expf(lrelu(ash + adh) - mh) * inv;
        float4 raw = *(const float4*)&g_hh2[dst * 128 + lane * 4];
        const __nv_bfloat162* bp = (const __nv_bfloat162*)&raw;
        float2 f0 = __bfloat1622float2(bp[0]);
        float2 f1 = __bfloat1622float2(bp[1]);
        float2 f2 = __bfloat1622float2(bp[2]);
        float2 f3 = __bfloat1622float2(bp[3]);
        a0 += f0.x * al; a1 += f0.y * al; a2 += f1.x * al; a3 += f1.y * al;
        a4 += f2.x * al; a5 += f2.y * al; a6 += f3.x * al; a7 += f3.y * al;
    }
    for (int e0 = r0; e0 < r1; e0 += 32) {
        int idx = e0 + lane;
        int sv = (idx < r1) ? g_csrsrc[idx] : 0;
        int cnt = min(32, r1 - e0);
        for (int j = 0; j < cnt; j++) {
            int src = __shfl_sync(0xffffffffu, sv, j);
            float ash = g_as[src * 4 + head];
            float al  = __expf(lrelu(ash + adh) - mh) * inv;
            float4 raw = *(const float4*)&g_hh2[src * 128 + lane * 4];
            const __nv_bfloat162* bp = (const __nv_bfloat162*)&raw;
            float2 f0 = __bfloat1622float2(bp[0]);
            float2 f1 = __bfloat1622float2(bp[1]);
            float2 f2 = __bfloat1622float2(bp[2]);
            float2 f3 = __bfloat1622float2(bp[3]);
            a0 += f0.x * al; a1 += f0.y * al; a2 += f1.x * al; a3 += f1.y * al;
            a4 += f2.x * al; a5 += f2.y * al; a6 += f3.x * al; a7 += f3.y * al;
        }
    }
    float4* out4 = (float4*)g_gat;
    out4[dst * 64 + lane * 2]     = make_float4(a0, a1, a2, a3);
    out4[dst * 64 + lane * 2 + 1] = make_float4(a4, a5, a6, a7);
}

// ---------------- pooling (batch is sorted) ----------------
__global__ void k_gstart(const int* __restrict__ batch) {
    int n = blockIdx.x * blockDim.x + threadIdx.x;
    if (n >= N_NODES) return;
    int b = batch[n];
    if (n == 0)
        for (int g = 0; g <= b; g++) g_gstart[g] = 0;
    if (n == N_NODES - 1) {
        for (int g = b + 1; g <= NG; g++) g_gstart[g] = N_NODES;
    } else {
        int b2 = batch[n + 1];
        for (int g = b + 1; g <= b2; g++) g_gstart[g] = n + 1;
    }
}

__global__ void k_pool(const float* __restrict__ bg) {
    int g = blockIdx.x, cb = blockIdx.y;
    int c    = threadIdx.x & 63;
    int slot = threadIdx.x >> 6;   // 0..3
    int st = g_gstart[g], en = g_gstart[g + 1];
    float acc = 0.f;
    for (int n = st + slot; n < en; n += 4)
        acc += g_gat[n * 256 + cb * 64 + c];
    __shared__ float sm[256];
    sm[threadIdx.x] = acc;
    __syncthreads();
    if (slot == 0) {
        float tot = sm[c] + sm[64 + c] + sm[128 + c] + sm[192 + c];
        int cnt = en - st;
        float v = (cnt > 0) ? tot / (float)cnt + bg[cb * 64 + c] : 0.f;
        g_pool[g * 256 + cb * 64 + c] = v;
    }
}

// ---------------- final MLP ----------------
__global__ void k_mlp(const float* __restrict__ Wf1, const float* __restrict__ bf1,
                      const float* __restrict__ Wf2, const float* __restrict__ bf2,
                      float* __restrict__ out) {
    int g = blockIdx.x;
    int j = threadIdx.x;   // 64 threads
    float acc = bf1[j];
    const float* p = &g_pool[g * 256];
    for (int c = 0; c < 256; c++)
        acc += p[c] * Wf1[c * 64 + j];
    float z = fmaxf(acc, 0.f) * Wf2[j];
#pragma unroll
    for (int off = 16; off > 0; off >>= 1)
        z += __shfl_xor_sync(0xffffffffu, z, off);
    __shared__ float sm[2];
    if ((threadIdx.x & 31) == 0) sm[threadIdx.x >> 5] = z;
    __syncthreads();
    if (threadIdx.x == 0) out[g] = sm[0] + sm[1] + bf2[0];
}

// ---------------- launch ----------------
extern "C" void kernel_launch(void* const* d_in, const int* in_sizes, int n_in,
                              void* d_out, int out_size) {
    const float* x       = (const float*)d_in[0];
    const int*   ei      = (const int*)  d_in[1];
    const int*   batch   = (const int*)  d_in[2];
    const float* W1      = (const float*)d_in[3];
    const float* b1      = (const float*)d_in[4];
    const float* W2      = (const float*)d_in[5];
    const float* b2      = (const float*)d_in[6];
    const float* Wg      = (const float*)d_in[7];
    const float* att_src = (const float*)d_in[8];
    const float* att_dst = (const float*)d_in[9];
    const float* bg      = (const float*)d_in[10];
    const float* Wf1     = (const float*)d_in[11];
    const float* bf1     = (const float*)d_in[12];
    const float* Wf2     = (const float*)d_in[13];
    const float* bf2     = (const float*)d_in[14];
    float* out = (float*)d_out;

    // lazily created side-stream resources (first call is the non-captured
    // correctness run; creation happens there, never during capture)
    static cudaStream_t s1 = nullptr;
    static cudaEvent_t  ev_fork = nullptr, ev_csr = nullptr;
    static void* d_deg_ptr = nullptr;
    if (!s1) {
        cudaStreamCreateWithFlags(&s1, cudaStreamNonBlocking);
        cudaEventCreateWithFlags(&ev_fork, cudaEventDisableTiming);
        cudaEventCreateWithFlags(&ev_csr,  cudaEventDisableTiming);
        cudaGetSymbolAddress(&d_deg_ptr, g_deg);
    }

    dim3 gemm_grid1((N_NODES + 127) / 128, 1);
    dim3 gemm_grid4((N_NODES + 127) / 128, 4);
    int  warp_blocks = (N_NODES + 7) / 8;   // 8 warps / 256-thread block

    // fork: CSR chain on side stream, concurrent with GEMM1
    cudaEventRecord(ev_fork, 0);
    cudaStreamWaitEvent(s1, ev_fork, 0);

    cudaMemsetAsync(d_deg_ptr, 0, N_NODES * sizeof(int), s1);
    k_hist      <<<(N_EDGES / 4 + 255) / 256, 256, 0, s1>>>(ei);
    k_scan_local<<<NB_SCAN, 256, 0, s1>>>();
    k_scan_bsum <<<1, 256, 0, s1>>>();
    k_fixup     <<<NB_SCAN, 256, 0, s1>>>();
    k_scatter   <<<(N_EDGES / 4 + 255) / 256, 256, 0, s1>>>(ei);
    k_gstart    <<<(N_NODES + 255) / 256, 256, 0, s1>>>(batch);
    cudaEventRecord(ev_csr, s1);

    // main stream: GEMM1 overlaps the CSR build
    k_gemm<<<gemm_grid1, 256>>>(x, W1, F_INPUT, 64, 0);

    // join: aggregation needs CSR
    cudaStreamWaitEvent(0, ev_csr, 0);

    k_gcn <<<warp_blocks, 256>>>(b1);
    k_gemm<<<gemm_grid1, 256>>>(x, W2, 64, 64, 1);
    k_gcn <<<warp_blocks, 256>>>(b2);
    k_gemm<<<gemm_grid4, 256>>>(x, Wg, 64, 256, 2);
    k_att <<<warp_blocks, 256>>>(att_src, att_dst);
    k_gat <<<warp_blocks, 256>>>();
    k_pool<<<dim3(NG, 4), 256>>>(bg);
    k_mlp <<<NG, 64>>>(Wf1, bf1, Wf2, bf2, out);
}

// round 8
// speedup vs baseline: 1.7876x; 1.3993x over previous
#include <cuda_runtime.h>
#include <cuda_bf16.h>
#include <cstdint>

#define N_NODES 50000
#define N_EDGES 800000
#define F_INPUT 256
#define HID     64
#define NHEADS  4
#define NG      64
#define NB_SCAN 196   // ceil(50000/256)

// ---------------- scratch (device globals: no allocation allowed) ----------------
__device__ int   g_deg[N_NODES];
__device__ float g_dinv[N_NODES];
__device__ int   g_rowptr[N_NODES + 1];
__device__ int   g_cursor[N_NODES];
__device__ int   g_csrsrc[N_EDGES];
__device__ int   g_bsum[256];
__device__ int   g_boff[256];
__device__ __nv_bfloat162 g_t2[N_NODES * 32];         // GEMM out (64 ch as bf16 pairs)
__device__ float g_h [N_NODES * HID];                 // layer activations (fp32)
__device__ __nv_bfloat162 g_hh2[N_NODES * 128];       // h @ Wg, bf16 pairs (256 ch)
__device__ float g_as[N_NODES * NHEADS];              // attention src logits
__device__ float g_ad[N_NODES * NHEADS];              // attention dst logits
__device__ float g_gat[N_NODES * NHEADS * HID];       // GAT output
__device__ float g_pool[NG * NHEADS * HID];
__device__ int   g_gstart[NG + 1];

__device__ __forceinline__ float lrelu(float x) { return x > 0.f ? x : 0.2f * x; }

// ---------------- CSR construction ----------------
__global__ void k_hist(const int* __restrict__ ei) {
    int t = blockIdx.x * blockDim.x + threadIdx.x;
    int e = t * 4;
    if (e < N_EDGES) {
        int4 d = *(const int4*)&ei[N_EDGES + e];
        atomicAdd(&g_deg[d.x], 1);
        atomicAdd(&g_deg[d.y], 1);
        atomicAdd(&g_deg[d.z], 1);
        atomicAdd(&g_deg[d.w], 1);
    }
}

// block-local exclusive scan of degrees
__global__ void k_scan_local() {
    __shared__ int sm[256];
    int t = threadIdx.x;
    int i = blockIdx.x * 256 + t;
    int d = (i < N_NODES) ? g_deg[i] : 0;
    sm[t] = d;
    __syncthreads();
    for (int off = 1; off < 256; off <<= 1) {
        int u = (t >= off) ? sm[t - off] : 0;
        __syncthreads();
        sm[t] += u;
        __syncthreads();
    }
    int incl = sm[t];
    if (i < N_NODES) {
        g_rowptr[i] = incl - d;           // local exclusive prefix (fixed up later)
        g_dinv[i]   = rsqrtf((float)(d + 1));
    }
    if (t == 255) g_bsum[blockIdx.x] = incl;
}

// scan the 196 block sums (single block)
__global__ void k_scan_bsum() {
    __shared__ int sm[256];
    int t = threadIdx.x;
    int v = (t < NB_SCAN) ? g_bsum[t] : 0;
    sm[t] = v;
    __syncthreads();
    for (int off = 1; off < 256; off <<= 1) {
        int u = (t >= off) ? sm[t - off] : 0;
        __syncthreads();
        sm[t] += u;
        __syncthreads();
    }
    g_boff[t] = sm[t] - v;
    if (t == 0) g_rowptr[N_NODES] = N_EDGES;
}

__global__ void k_fixup() {
    int i = blockIdx.x * 256 + threadIdx.x;
    if (i < N_NODES) {
        int r = g_rowptr[i] + g_boff[blockIdx.x];
        g_rowptr[i] = r;
        g_cursor[i] = r;
    }
}

__global__ void k_scatter(const int* __restrict__ ei) {
    int t = blockIdx.x * blockDim.x + threadIdx.x;
    int e = t * 4;
    if (e < N_EDGES) {
        int4 s = *(const int4*)&ei[e];
        int4 d = *(const int4*)&ei[N_EDGES + e];
        g_csrsrc[atomicAdd(&g_cursor[d.x], 1)] = s.x;
        g_csrsrc[atomicAdd(&g_cursor[d.y], 1)] = s.y;
        g_csrsrc[atomicAdd(&g_cursor[d.z], 1)] = s.z;
        g_csrsrc[atomicAdd(&g_cursor[d.w], 1)] = s.w;
    }
}

// ---------------- tensor-core GEMM (HMMA bf16, fp32 accum) ----------------------
// C[128 x 64-tile] = A[128 x K] @ W[K x nCols], output bf16x2
// mode 0: A = ext (x),  C = g_t2  (K=256, nCols=64)
// mode 1: A = g_h,      C = g_t2  (K=64,  nCols=64)
// mode 2: A = g_h,      C = g_hh2 (K=64,  nCols=256)
#define APAD 40   // bf16 per A smem row (32 used)
#define BPAD 72   // bf16 per B smem row (64 used)

__device__ __forceinline__ void ldsm_x4(unsigned* r, unsigned addr) {
    asm volatile("ldmatrix.sync.aligned.m8n8.x4.shared.b16 {%0,%1,%2,%3}, [%4];"
                 : "=r"(r[0]), "=r"(r[1]), "=r"(r[2]), "=r"(r[3]) : "r"(addr));
}
__device__ __forceinline__ void ldsm_x4_t(unsigned* r, unsigned addr) {
    asm volatile("ldmatrix.sync.aligned.m8n8.x4.trans.shared.b16 {%0,%1,%2,%3}, [%4];"
                 : "=r"(r[0]), "=r"(r[1]), "=r"(r[2]), "=r"(r[3]) : "r"(addr));
}
__device__ __forceinline__ void mma_bf16(float* c, const unsigned* a,
                                         unsigned b0, unsigned b1) {
    asm volatile(
        "mma.sync.aligned.m16n8k16.row.col.f32.bf16.bf16.f32 "
        "{%0,%1,%2,%3}, {%4,%5,%6,%7}, {%8,%9}, {%0,%1,%2,%3};"
        : "+f"(c[0]), "+f"(c[1]), "+f"(c[2]), "+f"(c[3])
        : "r"(a[0]), "r"(a[1]), "r"(a[2]), "r"(a[3]), "r"(b0), "r"(b1));
}

__global__ __launch_bounds__(256) void k_gemm(const float* __restrict__ Aext,
                                              const float* __restrict__ W,
                                              int K, int nCols, int mode) {
    const float* __restrict__ A = (mode == 0) ? Aext : g_h;

    __shared__ __nv_bfloat16 As[128 * APAD];   // 10240 B
    __shared__ __nv_bfloat16 Bs[32 * BPAD];    //  4608 B

    int tid  = threadIdx.x;
    int lane = tid & 31, warp = tid >> 5;
    int wr = warp >> 1, wc = warp & 1;         // 4 x 2 warp grid
    int m0 = blockIdx.x * 128;
    int colb = blockIdx.y * 64;

    unsigned As_base = (unsigned)__cvta_generic_to_shared(As);
    unsigned Bs_base = (unsigned)__cvta_generic_to_shared(Bs);

    float c[2][4][4] = {};                     // [m16][n8][frag]

    for (int k0 = 0; k0 < K; k0 += 32) {
        // A tile: 128 x 32 fp32 -> bf16 smem (4 float4 per thread)
#pragma unroll
        for (int i = 0; i < 4; i++) {
            int li  = i * 256 + tid;           // 0..1023
            int row = li >> 3, seg = li & 7;
            float4 av = make_float4(0.f, 0.f, 0.f, 0.f);
            int grow = m0 + row;
            if (grow < N_NODES)
                av = *(const float4*)&A[(long)grow * K + k0 + seg * 4];
            __nv_bfloat162 p0 = __floats2bfloat162_rn(av.x, av.y);
            __nv_bfloat162 p1 = __floats2bfloat162_rn(av.z, av.w);
            *(__nv_bfloat162*)&As[row * APAD + seg * 4]     = p0;
            *(__nv_bfloat162*)&As[row * APAD + seg * 4 + 2] = p1;
        }
        // B tile: 32 x 64 fp32 -> bf16 smem (2 float4 per thread)
#pragma unroll
        for (int i = 0; i < 2; i++) {
            int li  = i * 256 + tid;           // 0..511
            int row = li >> 4, seg = li & 15;
            float4 wv = *(const float4*)&W[(long)(k0 + row) * nCols + colb + seg * 4];
            __nv_bfloat162 p0 = __floats2bfloat162_rn(wv.x, wv.y);
            __nv_bfloat162 p1 = __floats2bfloat162_rn(wv.z, wv.w);
            *(__nv_bfloat162*)&Bs[row * BPAD + seg * 4]     = p0;
            *(__nv_bfloat162*)&Bs[row * BPAD + seg * 4 + 2] = p1;
        }
        __syncthreads();

#pragma unroll
        for (int kk = 0; kk < 2; kk++) {       // two k16 steps
            int k16 = kk * 16;
            unsigned a[2][4], b[2][4];
            int arow = wr * 32 + (lane & 15);
            int acol = k16 + (lane >> 4) * 8;
#pragma unroll
            for (int mi = 0; mi < 2; mi++)
                ldsm_x4(a[mi], As_base + ((arow + mi * 16) * APAD + acol) * 2);
            int brow = k16 + (lane & 15);
#pragma unroll
            for (int ni = 0; ni < 2; ni++) {
                int bcol = wc * 32 + ni * 16 + (lane >> 4) * 8;
                ldsm_x4_t(b[ni], Bs_base + (brow * BPAD + bcol) * 2);
            }
#pragma unroll
            for (int mi = 0; mi < 2; mi++)
#pragma unroll
                for (int j = 0; j < 4; j++)
                    mma_bf16(c[mi][j], a[mi], b[j >> 1][(j & 1) * 2],
                             b[j >> 1][(j & 1) * 2 + 1]);
        }
        __syncthreads();
    }

    // epilogue: C fragment (row = t/4 [,+8], col = (t%4)*2,+1) -> bf16x2 stores
    __nv_bfloat162* outp = (mode == 2) ? g_hh2 : g_t2;
    int ostride = (mode == 2) ? 128 : 32;
    int obase   = (mode == 2) ? (colb >> 1) : 0;
    int trow = lane >> 2, tq = lane & 3;
#pragma unroll
    for (int mi = 0; mi < 2; mi++) {
#pragma unroll
        for (int j = 0; j < 4; j++) {
            int row  = m0 + wr * 32 + mi * 16 + trow;
            int cidx = obase + wc * 16 + j * 4 + tq;
            if (row < N_NODES)
                outp[row * ostride + cidx] = __floats2bfloat162_rn(c[mi][j][0], c[mi][j][1]);
            if (row + 8 < N_NODES)
                outp[(row + 8) * ostride + cidx] = __floats2bfloat162_rn(c[mi][j][2], c[mi][j][3]);
        }
    }
}

// ---------------- GCN aggregation: h = relu(D^-1/2 A' D^-1/2 t + b) --------------
// warp per destination; lane owns channels {2*lane, 2*lane+1} (bf16x2 loads)
__global__ void k_gcn(const float* __restrict__ bias) {
    int warp = (blockIdx.x * blockDim.x + threadIdx.x) >> 5;
    int lane = threadIdx.x & 31;
    if (warp >= N_NODES) return;
    int dst = warp;
    int r0 = g_rowptr[dst], r1 = g_rowptr[dst + 1];
    float wd = g_dinv[dst];
    const __nv_bfloat162* __restrict__ t2 = g_t2;
    float2 f = __bfloat1622float2(t2[dst * 32 + lane]);   // self-loop
    float acc0 = f.x * wd;
    float acc1 = f.y * wd;
    for (int e0 = r0; e0 < r1; e0 += 32) {
        int idx = e0 + lane;
        int s = 0; float w = 0.f;
        if (idx < r1) { s = g_csrsrc[idx]; w = g_dinv[s]; }
        int cnt = min(32, r1 - e0);
        for (int j = 0; j < cnt; j++) {
            int   ss = __shfl_sync(0xffffffffu, s, j);
            float ww = __shfl_sync(0xffffffffu, w, j);
            float2 v = __bfloat1622float2(t2[ss * 32 + lane]);
            acc0 += v.x * ww;
            acc1 += v.y * ww;
        }
    }
    float2 b = *(const float2*)&bias[2 * lane];
    float2 o;
    o.x = fmaxf(acc0 * wd + b.x, 0.f);
    o.y = fmaxf(acc1 * wd + b.y, 0.f);
    *(float2*)&g_h[dst * 64 + 2 * lane] = o;
}

// ---------------- attention logits from bf16 hh ----------------
__global__ void k_att(const float* __restrict__ att_src, const float* __restrict__ att_dst) {
    int warp = (blockIdx.x * blockDim.x + threadIdx.x) >> 5;
    int lane = threadIdx.x & 31;
    if (warp >= N_NODES) return;
    int n = warp;
    int head = lane >> 3;
    int q    = lane & 7;
    float4 raw = *(const float4*)&g_hh2[n * 128 + lane * 4];   // 8 channels
    const __nv_bfloat162* bp = (const __nv_bfloat162*)&raw;
    float2 f0 = __bfloat1622float2(bp[0]);
    float2 f1 = __bfloat1622float2(bp[1]);
    float2 f2 = __bfloat1622float2(bp[2]);
    float2 f3 = __bfloat1622float2(bp[3]);
    const float4* s4 = (const float4*)att_src;
    const float4* d4 = (const float4*)att_dst;
    float4 a1 = s4[head * 16 + q * 2], a2 = s4[head * 16 + q * 2 + 1];
    float4 b1 = d4[head * 16 + q * 2], b2 = d4[head * 16 + q * 2 + 1];
    float ps = f0.x * a1.x + f0.y * a1.y + f1.x * a1.z + f1.y * a1.w
             + f2.x * a2.x + f2.y * a2.y + f3.x * a2.z + f3.y * a2.w;
    float pd = f0.x * b1.x + f0.y * b1.y + f1.x * b1.z + f1.y * b1.w
             + f2.x * b2.x + f2.y * b2.y + f3.x * b2.z + f3.y * b2.w;
#pragma unroll
    for (int off = 1; off < 8; off <<= 1) {
        ps += __shfl_xor_sync(0xffffffffu, ps, off);
        pd += __shfl_xor_sync(0xffffffffu, pd, off);
    }
    if (q == 0) {
        g_as[n * 4 + head] = ps;
        g_ad[n * 4 + head] = pd;
    }
}

__device__ __forceinline__ void onl(float& m, float& s, float e) {
    if (e > m) { s = s * __expf(m - e) + 1.f; m = e; }
    else       { s += __expf(e - m); }
}
__device__ __forceinline__ void comb(float& m1, float& s1, float m2, float s2) {
    if (m2 > m1) { s1 = s1 * __expf(m1 - m2) + s2; m1 = m2; }
    else         { s1 += s2 * __expf(m2 - m1); }
}

// ---------------- GAT: per-dst online softmax + weighted bf16 gather ----------------
__global__ void k_gat() {
    int warp = (blockIdx.x * blockDim.x + threadIdx.x) >> 5;
    int lane = threadIdx.x & 31;
    if (warp >= N_NODES) return;
    int dst = warp;
    int r0 = g_rowptr[dst], r1 = g_rowptr[dst + 1];
    const float4* as4 = (const float4*)g_as;
    float4 adv = ((const float4*)g_ad)[dst];

    // phase 1: per-head (max, sum), lane-parallel over edges
    float m0 = -1e30f, m1 = -1e30f, m2 = -1e30f, m3 = -1e30f;
    float s0 = 0.f, s1 = 0.f, s2 = 0.f, s3 = 0.f;
    for (int e = r0 + lane; e < r1; e += 32) {
        int src = g_csrsrc[e];
        float4 av = as4[src];
        onl(m0, s0, lrelu(av.x + adv.x));
        onl(m1, s1, lrelu(av.y + adv.y));
        onl(m2, s2, lrelu(av.z + adv.z));
        onl(m3, s3, lrelu(av.w + adv.w));
    }
    if (lane == 0) {   // self-loop
        float4 av = as4[dst];
        onl(m0, s0, lrelu(av.x + adv.x));
        onl(m1, s1, lrelu(av.y + adv.y));
        onl(m2, s2, lrelu(av.z + adv.z));
        onl(m3, s3, lrelu(av.w + adv.w));
    }
#pragma unroll
    for (int off = 16; off > 0; off >>= 1) {
        float mm, ss;
        mm = __shfl_down_sync(0xffffffffu, m0, off); ss = __shfl_down_sync(0xffffffffu, s0, off); comb(m0, s0, mm, ss);
        mm = __shfl_down_sync(0xffffffffu, m1, off); ss = __shfl_down_sync(0xffffffffu, s1, off); comb(m1, s1, mm, ss);
        mm = __shfl_down_sync(0xffffffffu, m2, off); ss = __shfl_down_sync(0xffffffffu, s2, off); comb(m2, s2, mm, ss);
        mm = __shfl_down_sync(0xffffffffu, m3, off); ss = __shfl_down_sync(0xffffffffu, s3, off); comb(m3, s3, mm, ss);
    }
    m0 = __shfl_sync(0xffffffffu, m0, 0); s0 = __shfl_sync(0xffffffffu, s0, 0);
    m1 = __shfl_sync(0xffffffffu, m1, 0); s1 = __shfl_sync(0xffffffffu, s1, 0);
    m2 = __shfl_sync(0xffffffffu, m2, 0); s2 = __shfl_sync(0xffffffffu, s2, 0);
    m3 = __shfl_sync(0xffffffffu, m3, 0); s3 = __shfl_sync(0xffffffffu, s3, 0);

    // phase 2: channel-parallel weighted gather (bf16 hh); lane owns 8 ch of its head
    int head = lane >> 3;
    float mh  = head == 0 ? m0 : head == 1 ? m1 : head == 2 ? m2 : m3;
    float sh  = head == 0 ? s0 : head == 1 ? s1 : head == 2 ? s2 : s3;
    float adh = head == 0 ? adv.x : head == 1 ? adv.y : head == 2 ? adv.z : adv.w;
    float inv = 1.f / sh;

    float a0 = 0.f, a1 = 0.f, a2 = 0.f, a3 = 0.f, a4 = 0.f, a5 = 0.f, a6 = 0.f, a7 = 0.f;
    {   // self-loop
        float ash = g_as[dst * 4 + head];
        float al  = __expf(lrelu(ash + adh) - mh) * inv;
        float4 raw = *(const float4*)&g_hh2[dst * 128 + lane * 4];
        const __nv_bfloat162* bp = (const __nv_bfloat162*)&raw;
        float2 f0 = __bfloat1622float2(bp[0]);
        float2 f1 = __bfloat1622float2(bp[1]);
        float2 f2 = __bfloat1622float2(bp[2]);
        float2 f3 = __bfloat1622float2(bp[3]);
        a0 += f0.x * al; a1 += f0.y * al; a2 += f1.x * al; a3 += f1.y * al;
        a4 += f2.x * al; a5 += f2.y * al; a6 += f3.x * al; a7 += f3.y * al;
    }
    for (int e0 = r0; e0 < r1; e0 += 32) {
        int idx = e0 + lane;
        int sv = (idx < r1) ? g_csrsrc[idx] : 0;
        int cnt = min(32, r1 - e0);
        for (int j = 0; j < cnt; j++) {
            int src = __shfl_sync(0xffffffffu, sv, j);
            float ash = g_as[src * 4 + head];
            float al  = __expf(lrelu(ash + adh) - mh) * inv;
            float4 raw = *(const float4*)&g_hh2[src * 128 + lane * 4];
            const __nv_bfloat162* bp = (const __nv_bfloat162*)&raw;
            float2 f0 = __bfloat1622float2(bp[0]);
            float2 f1 = __bfloat1622float2(bp[1]);
            float2 f2 = __bfloat1622float2(bp[2]);
            float2 f3 = __bfloat1622float2(bp[3]);
            a0 += f0.x * al; a1 += f0.y * al; a2 += f1.x * al; a3 += f1.y * al;
            a4 += f2.x * al; a5 += f2.y * al; a6 += f3.x * al; a7 += f3.y * al;
        }
    }
    float4* out4 = (float4*)g_gat;
    out4[dst * 64 + lane * 2]     = make_float4(a0, a1, a2, a3);
    out4[dst * 64 + lane * 2 + 1] = make_float4(a4, a5, a6, a7);
}

// ---------------- pooling (batch is sorted) ----------------
__global__ void k_gstart(const int* __restrict__ batch) {
    int n = blockIdx.x * blockDim.x + threadIdx.x;
    if (n >= N_NODES) return;
    int b = batch[n];
    if (n == 0)
        for (int g = 0; g <= b; g++) g_gstart[g] = 0;
    if (n == N_NODES - 1) {
        for (int g = b + 1; g <= NG; g++) g_gstart[g] = N_NODES;
    } else {
        int b2 = batch[n + 1];
        for (int g = b + 1; g <= b2; g++) g_gstart[g] = n + 1;
    }
}

__global__ void k_pool(const float* __restrict__ bg) {
    int g = blockIdx.x, cb = blockIdx.y;
    int c    = threadIdx.x & 63;
    int slot = threadIdx.x >> 6;   // 0..3
    int st = g_gstart[g], en = g_gstart[g + 1];
    float acc = 0.f;
    for (int n = st + slot; n < en; n += 4)
        acc += g_gat[n * 256 + cb * 64 + c];
    __shared__ float sm[256];
    sm[threadIdx.x] = acc;
    __syncthreads();
    if (slot == 0) {
        float tot = sm[c] + sm[64 + c] + sm[128 + c] + sm[192 + c];
        int cnt = en - st;
        float v = (cnt > 0) ? tot / (float)cnt + bg[cb * 64 + c] : 0.f;
        g_pool[g * 256 + cb * 64 + c] = v;
    }
}

// ---------------- final MLP ----------------
__global__ void k_mlp(const float* __restrict__ Wf1, const float* __restrict__ bf1,
                      const float* __restrict__ Wf2, const float* __restrict__ bf2,
                      float* __restrict__ out) {
    int g = blockIdx.x;
    int j = threadIdx.x;   // 64 threads
    float acc = bf1[j];
    const float* p = &g_pool[g * 256];
    for (int c = 0; c < 256; c++)
        acc += p[c] * Wf1[c * 64 + j];
    float z = fmaxf(acc, 0.f) * Wf2[j];
#pragma unroll
    for (int off = 16; off > 0; off >>= 1)
        z += __shfl_xor_sync(0xffffffffu, z, off);
    __shared__ float sm[2];
    if ((threadIdx.x & 31) == 0) sm[threadIdx.x >> 5] = z;
    __syncthreads();
    if (threadIdx.x == 0) out[g] = sm[0] + sm[1] + bf2[0];
}

// ---------------- launch ----------------
extern "C" void kernel_launch(void* const* d_in, const int* in_sizes, int n_in,
                              void* d_out, int out_size) {
    const float* x       = (const float*)d_in[0];
    const int*   ei      = (const int*)  d_in[1];
    const int*   batch   = (const int*)  d_in[2];
    const float* W1      = (const float*)d_in[3];
    const float* b1      = (const float*)d_in[4];
    const float* W2      = (const float*)d_in[5];
    const float* b2      = (const float*)d_in[6];
    const float* Wg      = (const float*)d_in[7];
    const float* att_src = (const float*)d_in[8];
    const float* att_dst = (const float*)d_in[9];
    const float* bg      = (const float*)d_in[10];
    const float* Wf1     = (const float*)d_in[11];
    const float* bf1     = (const float*)d_in[12];
    const float* Wf2     = (const float*)d_in[13];
    const float* bf2     = (const float*)d_in[14];
    float* out = (float*)d_out;

    // lazily created side-stream resources (first call is the non-captured
    // correctness run; creation happens there, never during capture)
    static cudaStream_t s1 = nullptr;
    static cudaEvent_t  ev_fork = nullptr, ev_csr = nullptr;
    static void* d_deg_ptr = nullptr;
    if (!s1) {
        cudaStreamCreateWithFlags(&s1, cudaStreamNonBlocking);
        cudaEventCreateWithFlags(&ev_fork, cudaEventDisableTiming);
        cudaEventCreateWithFlags(&ev_csr,  cudaEventDisableTiming);
        cudaGetSymbolAddress(&d_deg_ptr, g_deg);
    }

    dim3 gemm_grid1((N_NODES + 127) / 128, 1);
    dim3 gemm_grid4((N_NODES + 127) / 128, 4);
    int  warp_blocks = (N_NODES + 7) / 8;   // 8 warps / 256-thread block

    // fork: CSR chain on side stream, concurrent with GEMM1
    cudaEventRecord(ev_fork, 0);
    cudaStreamWaitEvent(s1, ev_fork, 0);

    cudaMemsetAsync(d_deg_ptr, 0, N_NODES * sizeof(int), s1);
    k_hist      <<<(N_EDGES / 4 + 255) / 256, 256, 0, s1>>>(ei);
    k_scan_local<<<NB_SCAN, 256, 0, s1>>>();
    k_scan_bsum <<<1, 256, 0, s1>>>();
    k_fixup     <<<NB_SCAN, 256, 0, s1>>>();
    k_scatter   <<<(N_EDGES / 4 + 255) / 256, 256, 0, s1>>>(ei);
    k_gstart    <<<(N_NODES + 255) / 256, 256, 0, s1>>>(batch);
    cudaEventRecord(ev_csr, s1);

    // main stream: GEMM1 overlaps the CSR build
    k_gemm<<<gemm_grid1, 256>>>(x, W1, F_INPUT, 64, 0);

    // join: aggregation needs CSR
    cudaStreamWaitEvent(0, ev_csr, 0);

    k_gcn <<<warp_blocks, 256>>>(b1);
    k_gemm<<<gemm_grid1, 256>>>(x, W2, 64, 64, 1);
    k_gcn <<<warp_blocks, 256>>>(b2);
    k_gemm<<<gemm_grid4, 256>>>(x, Wg, 64, 256, 2);
    k_att <<<warp_blocks, 256>>>(att_src, att_dst);
    k_gat <<<warp_blocks, 256>>>();
    k_pool<<<dim3(NG, 4), 256>>>(bg);
    k_mlp <<<NG, 64>>>(Wf1, bf1, Wf2, bf2, out);
}